// round 11
// baseline (speedup 1.0000x reference)
#include <cuda_runtime.h>
#include <cuda_fp16.h>
#include <cstdint>

#define BB 16
#define PP 2048
#define HB 2048
#define DB 1024

// ---- device scratch (static __device__ globals) ----
__device__ __half g_Eh[(size_t)BB * PP * HB];    // 128 MB  exp(sim)*mask, fp16
__device__ __half g_Qh[(size_t)BB * PP * DB];    //  64 MB  premise fp16
__device__ __half g_Kh[(size_t)BB * HB * DB];    //  64 MB  hypothesis fp16 [b,h,d]
__device__ __half g_Vth[(size_t)BB * DB * HB];   //  64 MB  hypothesis transposed [b,d,h] fp16
__device__ float g_psum[(size_t)BB * PP * 16];
__device__ float g_rowsum[(size_t)BB * PP];
__device__ int g_hlen[BB];
__device__ int g_plen[BB];

// ---- helpers ----
__device__ __forceinline__ uint32_t smem_u32(const void* p) {
    uint32_t a;
    asm("{ .reg .u64 t; cvta.to.shared.u64 t, %1; cvt.u32.u64 %0, t; }" : "=r"(a) : "l"(p));
    return a;
}

__device__ __forceinline__ void cp_async16(uint32_t dst, const void* src) {
    asm volatile("cp.async.cg.shared.global [%0], [%1], 16;" :: "r"(dst), "l"(src));
}

__device__ __forceinline__ void ldsm4(uint32_t& r0, uint32_t& r1, uint32_t& r2, uint32_t& r3,
                                      uint32_t addr) {
    asm volatile("ldmatrix.sync.aligned.m8n8.x4.shared.b16 {%0,%1,%2,%3}, [%4];"
                 : "=r"(r0), "=r"(r1), "=r"(r2), "=r"(r3) : "r"(addr));
}

__device__ __forceinline__ void mma16(float c[4], uint32_t a0, uint32_t a1, uint32_t a2,
                                      uint32_t a3, uint32_t b0, uint32_t b1) {
    asm volatile(
        "mma.sync.aligned.m16n8k16.row.col.f32.f16.f16.f32 "
        "{%0,%1,%2,%3}, {%4,%5,%6,%7}, {%8,%9}, {%0,%1,%2,%3};\n"
        : "+f"(c[0]), "+f"(c[1]), "+f"(c[2]), "+f"(c[3])
        : "r"(a0), "r"(a1), "r"(a2), "r"(a3), "r"(b0), "r"(b1));
}

// ---------------------------------------------------------------------------
// prep kernels
// ---------------------------------------------------------------------------
__global__ __launch_bounds__(256) void conv_premise(const float4* __restrict__ in) {
    uint2* outp = (uint2*)g_Qh;
    const int n4 = BB * PP * DB / 4;
    int i = blockIdx.x * 256 + threadIdx.x;
    const int stride = gridDim.x * 256;
    for (; i < n4; i += stride) {
        float4 v = in[i];
        __half2 lo = __floats2half2_rn(v.x, v.y);
        __half2 hi = __floats2half2_rn(v.z, v.w);
        uint2 o;
        o.x = *reinterpret_cast<uint32_t*>(&lo);
        o.y = *reinterpret_cast<uint32_t*>(&hi);
        outp[i] = o;
    }
}

__global__ void prep_hyp(const float* __restrict__ hyp) {
    __shared__ float t[32][33];
    const int b = blockIdx.z;
    const int h0 = blockIdx.x * 32, d0 = blockIdx.y * 32;
    const int tx = threadIdx.x, ty = threadIdx.y;   // (32, 8)
#pragma unroll
    for (int i = 0; i < 4; i++) {
        int h = ty + i * 8;
        size_t idx = ((size_t)b * HB + h0 + h) * DB + d0 + tx;
        float v = hyp[idx];
        g_Kh[idx] = __float2half_rn(v);
        t[tx][h] = v;
    }
    __syncthreads();
#pragma unroll
    for (int i = 0; i < 4; i++) {
        int d = ty + i * 8;
        g_Vth[((size_t)b * DB + d0 + d) * HB + h0 + tx] = __float2half_rn(t[d][tx]);
    }
}

// per-batch valid lengths from the prefix masks (sums of 0/1 are exact)
__global__ __launch_bounds__(256) void len_k(const float* __restrict__ hmask,
                                             const float* __restrict__ pmask) {
    const int b = blockIdx.x, tid = threadIdx.x;
    float s1 = 0.0f, s2 = 0.0f;
    for (int i = tid; i < HB; i += 256) s1 += hmask[(size_t)b * HB + i];
    for (int i = tid; i < PP; i += 256) s2 += pmask[(size_t)b * PP + i];
    __shared__ float r1[256], r2[256];
    r1[tid] = s1; r2[tid] = s2;
    __syncthreads();
    for (int o = 128; o > 0; o >>= 1) {
        if (tid < o) { r1[tid] += r1[tid + o]; r2[tid] += r2[tid + o]; }
        __syncthreads();
    }
    if (tid == 0) {
        g_hlen[b] = (int)(r1[0] + 0.5f);
        g_plen[b] = (int)(r2[0] + 0.5f);
    }
}

__global__ void rowsum_k() {
    int i = blockIdx.x * 256 + threadIdx.x;
    if (i < BB * PP) {
        float s = 0.0f;
#pragma unroll
        for (int j = 0; j < 16; j++) s += g_psum[(size_t)i * 16 + j];
        g_rowsum[i] = s;
    }
}

// ---------------------------------------------------------------------------
// fp16 mma.sync GEMM. CTA tile 128x128, 4 warps (2x2), warp tile 64x64.
// 32-half k-chunks, 3-stage cp.async pipeline, 3 CTAs/SM (regs capped at 170
// via launch_bounds) -> 3 warps/SMSP for tensor-pipe latency hiding.
// Mask-aware tile skipping via per-batch prefix-mask lengths.
// MODE 0: A=g_Qh, B=g_Kh (K=1024). Epilogue: E=exp(acc/32)*hmask -> g_Eh, psum.
// MODE 1: A=g_Eh, B=g_Vth (K truncated to ceil32(hlen)). out = acc*pmask/rowsum.
// ---------------------------------------------------------------------------
#define STAGE_B 20480u            // bytes per stage: (256 rows * 80B)
#define NSTAGE 3
#define SMEM_BYTES (NSTAGE * STAGE_B)   // 61440

template <int MODE>
__global__ __launch_bounds__(128, 3) void attn_gemm(const float* __restrict__ hmask,
                                                    const float* __restrict__ pmask,
                                                    float* __restrict__ outp) {
    constexpr int KD = MODE ? HB : DB;       // k extent in halfs
    constexpr int S = KD / 32;

    extern __shared__ float smf[];
    const uint32_t sbase = smem_u32(smf);

    const int tid = threadIdx.x;
    const int x = blockIdx.x, y = blockIdx.y, b = blockIdx.z;
    const int lane = tid & 31, w = tid >> 5;
    const int wm = w >> 1, wn = w & 1;       // 2x2 warps, each 64x64
    const int g = lane >> 2, tg = lane & 3;

    const size_t growbase = (size_t)b * PP + (size_t)y * 128;

    int Send = S;
    if (MODE == 0) {
        if (x * 128 >= g_hlen[b] || y * 128 >= g_plen[b]) return;
    } else {
        if (y * 128 >= g_plen[b]) {
            float4 z = make_float4(0.0f, 0.0f, 0.0f, 0.0f);
            float4* dst = (float4*)(outp + (growbase + tid) * DB + x * 128);
#pragma unroll
            for (int c = 0; c < 32; c++) dst[c] = z;
            return;
        }
        Send = (g_hlen[b] + 31) >> 5;        // E columns beyond hlen are zero
    }

    const __half* Ab = (MODE ? g_Eh : g_Qh) + ((size_t)b * PP + (size_t)y * 128) * KD;
    const __half* Bb = (MODE ? g_Vth : g_Kh) + (size_t)b * (size_t)(HB * DB)
                       + (size_t)x * 128 * KD;

    float acc[4][8][4];
#pragma unroll
    for (int mt = 0; mt < 4; mt++)
#pragma unroll
        for (int nt = 0; nt < 8; nt++)
#pragma unroll
            for (int i = 0; i < 4; i++) acc[mt][nt][i] = 0.0f;

    auto load_stage = [&](int s, int buf) {
        if (s < Send) {
            const int kc = s * 32;
            const uint32_t stb = sbase + (uint32_t)buf * STAGE_B;
#pragma unroll
            for (int i = 0; i < 4; i++) {
                int idx = i * 128 + tid;          // 0..511
                int r = idx >> 2, c = idx & 3;
                uint32_t d = stb + (uint32_t)r * 80 + (uint32_t)c * 16;
                cp_async16(d, Ab + (size_t)r * KD + kc + c * 8);
                cp_async16(d + STAGE_B / 2, Bb + (size_t)r * KD + kc + c * 8);
            }
        }
        asm volatile("cp.async.commit_group;" ::: "memory");
    };

    load_stage(0, 0);
    load_stage(1, 1);

    // per-lane ldmatrix byte offsets
    const uint32_t a_off = (uint32_t)(wm * 64 + (lane & 15)) * 80 + (uint32_t)(lane >> 4) * 16;
    const uint32_t b_off = STAGE_B / 2 +
        (uint32_t)(wn * 64 + ((lane >> 4) << 3) + (lane & 7)) * 80 +
        (uint32_t)((lane >> 3) & 1) * 16;

    int cbuf = 0, lbuf = 2;
#pragma unroll 1
    for (int s = 0; s < Send; s++) {
        asm volatile("cp.async.wait_group 1;" ::: "memory");
        __syncthreads();
        load_stage(s + 2, lbuf);

        const uint32_t stb = sbase + (uint32_t)cbuf * STAGE_B;
#pragma unroll
        for (int j = 0; j < 2; j++) {
            uint32_t bf[8][2];
#pragma unroll
            for (int ntp = 0; ntp < 4; ntp++) {
                uint32_t q0, q1, q2, q3;
                ldsm4(q0, q1, q2, q3, stb + b_off + (uint32_t)ntp * 1280 + (uint32_t)j * 32);
                bf[2 * ntp][0] = q0; bf[2 * ntp][1] = q1;
                bf[2 * ntp + 1][0] = q2; bf[2 * ntp + 1][1] = q3;
            }
#pragma unroll
            for (int mt = 0; mt < 4; mt++) {
                uint32_t a0, a1, a2, a3;
                ldsm4(a0, a1, a2, a3, stb + a_off + (uint32_t)mt * 1280 + (uint32_t)j * 32);
#pragma unroll
                for (int nt = 0; nt < 8; nt++)
                    mma16(acc[mt][nt], a0, a1, a2, a3, bf[nt][0], bf[nt][1]);
            }
        }
        cbuf = (cbuf == 2) ? 0 : cbuf + 1;
        lbuf = (lbuf == 2) ? 0 : lbuf + 1;
    }

    // ---- epilogue ----
    __syncthreads();

    if (MODE == 0) {
        const float* hm = hmask + (size_t)b * HB + x * 128;
        float ps[4][2];
#pragma unroll
        for (int mt = 0; mt < 4; mt++) { ps[mt][0] = 0.0f; ps[mt][1] = 0.0f; }

#pragma unroll
        for (int mt = 0; mt < 4; mt++) {
            const int r0 = wm * 64 + mt * 16 + g;
#pragma unroll
            for (int nt = 0; nt < 8; nt++) {
                const int col = wn * 64 + nt * 8 + 2 * tg;
                float2 m = *(const float2*)(hm + col);
                float e0 = (m.x != 0.0f) ? __expf(acc[mt][nt][0] * 0.03125f) : 0.0f;
                float e1 = (m.y != 0.0f) ? __expf(acc[mt][nt][1] * 0.03125f) : 0.0f;
                float e2 = (m.x != 0.0f) ? __expf(acc[mt][nt][2] * 0.03125f) : 0.0f;
                float e3 = (m.y != 0.0f) ? __expf(acc[mt][nt][3] * 0.03125f) : 0.0f;
                __half2 h01 = __floats2half2_rn(e0, e1);
                __half2 h23 = __floats2half2_rn(e2, e3);
                *(__half2*)(g_Eh + (growbase + r0) * HB + x * 128 + col) = h01;
                *(__half2*)(g_Eh + (growbase + r0 + 8) * HB + x * 128 + col) = h23;
                float2 f01 = __half22float2(h01);
                float2 f23 = __half22float2(h23);
                ps[mt][0] += f01.x + f01.y;
                ps[mt][1] += f23.x + f23.y;
            }
        }
#pragma unroll
        for (int mt = 0; mt < 4; mt++)
#pragma unroll
            for (int h = 0; h < 2; h++) {
                float v = ps[mt][h];
                v += __shfl_xor_sync(0xFFFFFFFFu, v, 1);
                v += __shfl_xor_sync(0xFFFFFFFFu, v, 2);
                if (tg == 0) {
                    int rloc = wm * 64 + mt * 16 + g + h * 8;
                    smf[rloc * 2 + wn] = v;
                }
            }
        __syncthreads();
        if (tid < 128) {
            float s2 = smf[tid * 2 + 0] + smf[tid * 2 + 1];
            g_psum[(growbase + tid) * 16 + x] = s2;
        }
    } else {
#pragma unroll
        for (int mt = 0; mt < 4; mt++) {
            const int r0 = wm * 64 + mt * 16 + g;
            const size_t grow0 = growbase + r0, grow1 = growbase + r0 + 8;
            const float pm0 = pmask[grow0], pm1 = pmask[grow1];
            const float s0 = (pm0 != 0.0f) ? pm0 / (g_rowsum[grow0] + 1e-13f) : 0.0f;
            const float s1 = (pm1 != 0.0f) ? pm1 / (g_rowsum[grow1] + 1e-13f) : 0.0f;
#pragma unroll
            for (int nt = 0; nt < 8; nt++) {
                const int col = x * 128 + wn * 64 + nt * 8 + 2 * tg;
                *(float2*)(outp + grow0 * DB + col) =
                    make_float2(acc[mt][nt][0] * s0, acc[mt][nt][1] * s0);
                *(float2*)(outp + grow1 * DB + col) =
                    make_float2(acc[mt][nt][2] * s1, acc[mt][nt][3] * s1);
            }
        }
    }
}

// ---------------------------------------------------------------------------
extern "C" void kernel_launch(void* const* d_in, const int* in_sizes, int n_in,
                              void* d_out, int out_size) {
    const float* Q     = (const float*)d_in[0];  // premise_batch    [B,P,D]
    const float* pmask = (const float*)d_in[1];  // premise_mask     [B,P]
    const float* HYP   = (const float*)d_in[2];  // hypothesis_batch [B,H,D]
    const float* hmask = (const float*)d_in[3];  // hypothesis_mask  [B,H]
    float* out = (float*)d_out;

    cudaFuncSetAttribute(attn_gemm<0>, cudaFuncAttributeMaxDynamicSharedMemorySize, SMEM_BYTES);
    cudaFuncSetAttribute(attn_gemm<1>, cudaFuncAttributeMaxDynamicSharedMemorySize, SMEM_BYTES);

    len_k<<<BB, 256>>>(hmask, pmask);
    conv_premise<<<4096, 256>>>((const float4*)Q);
    prep_hyp<<<dim3(HB / 32, DB / 32, BB), dim3(32, 8)>>>(HYP);
    attn_gemm<0><<<dim3(16, 16, 16), 128, SMEM_BYTES>>>(hmask, nullptr, nullptr);
    rowsum_k<<<BB * PP / 256, 256>>>();
    attn_gemm<1><<<dim3(8, 16, 16), 128, SMEM_BYTES>>>(nullptr, pmask, out);
}

// round 12
// speedup vs baseline: 1.1905x; 1.1905x over previous
#include <cuda_runtime.h>
#include <cuda_fp16.h>
#include <cstdint>

#define BB 16
#define PP 2048
#define HB 2048
#define DB 1024

// ---- device scratch (static __device__ globals) ----
__device__ __half g_Eh[(size_t)BB * PP * HB];    // 128 MB  exp(sim)*mask, fp16
__device__ __half g_Qh[(size_t)BB * PP * DB];    //  64 MB  premise fp16
__device__ __half g_Kh[(size_t)BB * HB * DB];    //  64 MB  hypothesis fp16 [b,h,d]
__device__ __half g_Vth[(size_t)BB * DB * HB];   //  64 MB  hypothesis transposed [b,d,h] fp16
__device__ float g_psum[(size_t)BB * PP * 16];
__device__ float g_rowsum[(size_t)BB * PP];
__device__ int g_hlen[BB];
__device__ int g_plen[BB];

// ---- helpers ----
__device__ __forceinline__ uint32_t smem_u32(const void* p) {
    uint32_t a;
    asm("{ .reg .u64 t; cvta.to.shared.u64 t, %1; cvt.u32.u64 %0, t; }" : "=r"(a) : "l"(p));
    return a;
}

__device__ __forceinline__ void cp_async16(uint32_t dst, const void* src) {
    asm volatile("cp.async.cg.shared.global [%0], [%1], 16;" :: "r"(dst), "l"(src));
}

__device__ __forceinline__ void ldsm4(uint32_t& r0, uint32_t& r1, uint32_t& r2, uint32_t& r3,
                                      uint32_t addr) {
    asm volatile("ldmatrix.sync.aligned.m8n8.x4.shared.b16 {%0,%1,%2,%3}, [%4];"
                 : "=r"(r0), "=r"(r1), "=r"(r2), "=r"(r3) : "r"(addr));
}

__device__ __forceinline__ void mma16(float c[4], uint32_t a0, uint32_t a1, uint32_t a2,
                                      uint32_t a3, uint32_t b0, uint32_t b1) {
    asm volatile(
        "mma.sync.aligned.m16n8k16.row.col.f32.f16.f16.f32 "
        "{%0,%1,%2,%3}, {%4,%5,%6,%7}, {%8,%9}, {%0,%1,%2,%3};\n"
        : "+f"(c[0]), "+f"(c[1]), "+f"(c[2]), "+f"(c[3])
        : "r"(a0), "r"(a1), "r"(a2), "r"(a3), "r"(b0), "r"(b1));
}

// ---------------------------------------------------------------------------
// prep kernels
// ---------------------------------------------------------------------------
__global__ __launch_bounds__(256) void conv_premise(const float4* __restrict__ in) {
    uint2* outp = (uint2*)g_Qh;
    const int n4 = BB * PP * DB / 4;
    int i = blockIdx.x * 256 + threadIdx.x;
    const int stride = gridDim.x * 256;
    for (; i < n4; i += stride) {
        float4 v = in[i];
        __half2 lo = __floats2half2_rn(v.x, v.y);
        __half2 hi = __floats2half2_rn(v.z, v.w);
        uint2 o;
        o.x = *reinterpret_cast<uint32_t*>(&lo);
        o.y = *reinterpret_cast<uint32_t*>(&hi);
        outp[i] = o;
    }
}

__global__ void prep_hyp(const float* __restrict__ hyp) {
    __shared__ float t[32][33];
    const int b = blockIdx.z;
    const int h0 = blockIdx.x * 32, d0 = blockIdx.y * 32;
    const int tx = threadIdx.x, ty = threadIdx.y;   // (32, 8)
#pragma unroll
    for (int i = 0; i < 4; i++) {
        int h = ty + i * 8;
        size_t idx = ((size_t)b * HB + h0 + h) * DB + d0 + tx;
        float v = hyp[idx];
        g_Kh[idx] = __float2half_rn(v);
        t[tx][h] = v;
    }
    __syncthreads();
#pragma unroll
    for (int i = 0; i < 4; i++) {
        int d = ty + i * 8;
        g_Vth[((size_t)b * DB + d0 + d) * HB + h0 + tx] = __float2half_rn(t[d][tx]);
    }
}

// per-batch valid lengths from the prefix masks (sums of 0/1 are exact)
__global__ __launch_bounds__(256) void len_k(const float* __restrict__ hmask,
                                             const float* __restrict__ pmask) {
    const int b = blockIdx.x, tid = threadIdx.x;
    float s1 = 0.0f, s2 = 0.0f;
    for (int i = tid; i < HB; i += 256) s1 += hmask[(size_t)b * HB + i];
    for (int i = tid; i < PP; i += 256) s2 += pmask[(size_t)b * PP + i];
    __shared__ float r1[256], r2[256];
    r1[tid] = s1; r2[tid] = s2;
    __syncthreads();
    for (int o = 128; o > 0; o >>= 1) {
        if (tid < o) { r1[tid] += r1[tid + o]; r2[tid] += r2[tid + o]; }
        __syncthreads();
    }
    if (tid == 0) {
        g_hlen[b] = (int)(r1[0] + 0.5f);
        g_plen[b] = (int)(r2[0] + 0.5f);
    }
}

__global__ void rowsum_k() {
    int i = blockIdx.x * 256 + threadIdx.x;
    if (i < BB * PP) {
        float s = 0.0f;
#pragma unroll
        for (int j = 0; j < 16; j++) s += g_psum[(size_t)i * 16 + j];
        g_rowsum[i] = s;
    }
}

// ---------------------------------------------------------------------------
// fp16 mma.sync GEMM. CTA tile 128x128, 4 warps (2x2), warp tile 64x64.
// 32-half k-chunks in DENSE 64B rows with XOR swizzle
//   off(r, c16) = r*64 + ((c16 ^ ((r>>1)&3)) * 16)
// -> conflict-free cp.async stores AND ldmatrix reads (verified per 8-lane
// phase: all 32 banks hit exactly once). 4-stage pipeline, 3 CTAs/SM.
// MODE 0: A=g_Qh, B=g_Kh (K=1024). Epilogue: E=exp(acc/32)*hmask -> g_Eh, psum.
// MODE 1: A=g_Eh, B=g_Vth (K truncated to ceil32(hlen)). out = acc*pmask/rowsum.
// ---------------------------------------------------------------------------
#define OP_B 8192u                 // one operand per stage: 128 rows * 64B
#define STAGE_B 16384u
#define NSTAGE 4
#define SMEM_BYTES (NSTAGE * STAGE_B)   // 65536

template <int MODE>
__global__ __launch_bounds__(128, 3) void attn_gemm(const float* __restrict__ hmask,
                                                    const float* __restrict__ pmask,
                                                    float* __restrict__ outp) {
    constexpr int KD = MODE ? HB : DB;       // k extent in halfs
    constexpr int S = KD / 32;

    extern __shared__ float smf[];
    const uint32_t sbase = smem_u32(smf);

    const int tid = threadIdx.x;
    const int x = blockIdx.x, y = blockIdx.y, b = blockIdx.z;
    const int lane = tid & 31, w = tid >> 5;
    const int wm = w >> 1, wn = w & 1;       // 2x2 warps, each 64x64
    const int g = lane >> 2, tg = lane & 3;

    const size_t growbase = (size_t)b * PP + (size_t)y * 128;

    int Send = S;
    if (MODE == 0) {
        if (x * 128 >= g_hlen[b] || y * 128 >= g_plen[b]) return;
    } else {
        if (y * 128 >= g_plen[b]) {
            float4 z = make_float4(0.0f, 0.0f, 0.0f, 0.0f);
            float4* dst = (float4*)(outp + (growbase + tid) * DB + x * 128);
#pragma unroll
            for (int c = 0; c < 32; c++) dst[c] = z;
            return;
        }
        Send = (g_hlen[b] + 31) >> 5;        // E columns beyond hlen are zero
    }

    const __half* Ab = (MODE ? g_Eh : g_Qh) + ((size_t)b * PP + (size_t)y * 128) * KD;
    const __half* Bb = (MODE ? g_Vth : g_Kh) + (size_t)b * (size_t)(HB * DB)
                       + (size_t)x * 128 * KD;

    float acc[4][8][4];
#pragma unroll
    for (int mt = 0; mt < 4; mt++)
#pragma unroll
        for (int nt = 0; nt < 8; nt++)
#pragma unroll
            for (int i = 0; i < 4; i++) acc[mt][nt][i] = 0.0f;

    // cp.async swizzled destination offsets (r = idx>>2, c = idx&3)
    auto load_stage = [&](int s, int buf) {
        if (s < Send) {
            const int kc = s * 32;
            const uint32_t stb = sbase + (uint32_t)buf * STAGE_B;
#pragma unroll
            for (int i = 0; i < 4; i++) {
                int idx = i * 128 + tid;          // 0..511
                int r = idx >> 2, c = idx & 3;
                uint32_t sw = (uint32_t)(c ^ ((r >> 1) & 3));
                uint32_t d = stb + (uint32_t)r * 64 + sw * 16;
                cp_async16(d, Ab + (size_t)r * KD + kc + c * 8);
                cp_async16(d + OP_B, Bb + (size_t)r * KD + kc + c * 8);
            }
        }
        asm volatile("cp.async.commit_group;" ::: "memory");
    };

    load_stage(0, 0);
    load_stage(1, 1);
    load_stage(2, 2);

    // per-lane ldmatrix byte offsets (swizzle folded in; j toggles ^32)
    const int ra = wm * 64 + (lane & 15);
    const uint32_t a_c0 = (uint32_t)(((lane >> 4) ^ ((ra >> 1) & 3)) & 3);
    const uint32_t a_off0 = (uint32_t)ra * 64 + a_c0 * 16;
    const int rb = wn * 64 + ((lane >> 4) << 3) + (lane & 7);
    const uint32_t b_c0 = (uint32_t)((((lane >> 3) & 1) ^ ((rb >> 1) & 3)) & 3);
    const uint32_t b_off0 = OP_B + (uint32_t)rb * 64 + b_c0 * 16;

#pragma unroll 1
    for (int s = 0; s < Send; s++) {
        asm volatile("cp.async.wait_group 2;" ::: "memory");
        __syncthreads();
        load_stage(s + 3, (s + 3) & 3);

        const uint32_t stb = sbase + (uint32_t)(s & 3) * STAGE_B;
#pragma unroll
        for (int j = 0; j < 2; j++) {
            const uint32_t jx = (uint32_t)j << 5;   // ^32: swizzled k-half toggle
            uint32_t bf[8][2];
#pragma unroll
            for (int ntp = 0; ntp < 4; ntp++) {
                uint32_t q0, q1, q2, q3;
                ldsm4(q0, q1, q2, q3, stb + ((b_off0 + (uint32_t)ntp * 1024) ^ jx));
                bf[2 * ntp][0] = q0; bf[2 * ntp][1] = q1;
                bf[2 * ntp + 1][0] = q2; bf[2 * ntp + 1][1] = q3;
            }
#pragma unroll
            for (int mt = 0; mt < 4; mt++) {
                uint32_t a0, a1, a2, a3;
                ldsm4(a0, a1, a2, a3, stb + ((a_off0 + (uint32_t)mt * 1024) ^ jx));
#pragma unroll
                for (int nt = 0; nt < 8; nt++)
                    mma16(acc[mt][nt], a0, a1, a2, a3, bf[nt][0], bf[nt][1]);
            }
        }
    }

    // ---- epilogue ----
    __syncthreads();

    if (MODE == 0) {
        const float* hm = hmask + (size_t)b * HB + x * 128;
        float ps[4][2];
#pragma unroll
        for (int mt = 0; mt < 4; mt++) { ps[mt][0] = 0.0f; ps[mt][1] = 0.0f; }

#pragma unroll
        for (int mt = 0; mt < 4; mt++) {
            const int r0 = wm * 64 + mt * 16 + g;
#pragma unroll
            for (int nt = 0; nt < 8; nt++) {
                const int col = wn * 64 + nt * 8 + 2 * tg;
                float2 m = *(const float2*)(hm + col);
                float e0 = (m.x != 0.0f) ? __expf(acc[mt][nt][0] * 0.03125f) : 0.0f;
                float e1 = (m.y != 0.0f) ? __expf(acc[mt][nt][1] * 0.03125f) : 0.0f;
                float e2 = (m.x != 0.0f) ? __expf(acc[mt][nt][2] * 0.03125f) : 0.0f;
                float e3 = (m.y != 0.0f) ? __expf(acc[mt][nt][3] * 0.03125f) : 0.0f;
                __half2 h01 = __floats2half2_rn(e0, e1);
                __half2 h23 = __floats2half2_rn(e2, e3);
                *(__half2*)(g_Eh + (growbase + r0) * HB + x * 128 + col) = h01;
                *(__half2*)(g_Eh + (growbase + r0 + 8) * HB + x * 128 + col) = h23;
                float2 f01 = __half22float2(h01);
                float2 f23 = __half22float2(h23);
                ps[mt][0] += f01.x + f01.y;
                ps[mt][1] += f23.x + f23.y;
            }
        }
#pragma unroll
        for (int mt = 0; mt < 4; mt++)
#pragma unroll
            for (int h = 0; h < 2; h++) {
                float v = ps[mt][h];
                v += __shfl_xor_sync(0xFFFFFFFFu, v, 1);
                v += __shfl_xor_sync(0xFFFFFFFFu, v, 2);
                if (tg == 0) {
                    int rloc = wm * 64 + mt * 16 + g + h * 8;
                    smf[rloc * 2 + wn] = v;
                }
            }
        __syncthreads();
        if (tid < 128) {
            float s2 = smf[tid * 2 + 0] + smf[tid * 2 + 1];
            g_psum[(growbase + tid) * 16 + x] = s2;
        }
    } else {
#pragma unroll
        for (int mt = 0; mt < 4; mt++) {
            const int r0 = wm * 64 + mt * 16 + g;
            const size_t grow0 = growbase + r0, grow1 = growbase + r0 + 8;
            const float pm0 = pmask[grow0], pm1 = pmask[grow1];
            const float s0 = (pm0 != 0.0f) ? pm0 / (g_rowsum[grow0] + 1e-13f) : 0.0f;
            const float s1 = (pm1 != 0.0f) ? pm1 / (g_rowsum[grow1] + 1e-13f) : 0.0f;
#pragma unroll
            for (int nt = 0; nt < 8; nt++) {
                const int col = x * 128 + wn * 64 + nt * 8 + 2 * tg;
                *(float2*)(outp + grow0 * DB + col) =
                    make_float2(acc[mt][nt][0] * s0, acc[mt][nt][1] * s0);
                *(float2*)(outp + grow1 * DB + col) =
                    make_float2(acc[mt][nt][2] * s1, acc[mt][nt][3] * s1);
            }
        }
    }
}

// ---------------------------------------------------------------------------
extern "C" void kernel_launch(void* const* d_in, const int* in_sizes, int n_in,
                              void* d_out, int out_size) {
    const float* Q     = (const float*)d_in[0];  // premise_batch    [B,P,D]
    const float* pmask = (const float*)d_in[1];  // premise_mask     [B,P]
    const float* HYP   = (const float*)d_in[2];  // hypothesis_batch [B,H,D]
    const float* hmask = (const float*)d_in[3];  // hypothesis_mask  [B,H]
    float* out = (float*)d_out;

    cudaFuncSetAttribute(attn_gemm<0>, cudaFuncAttributeMaxDynamicSharedMemorySize, SMEM_BYTES);
    cudaFuncSetAttribute(attn_gemm<1>, cudaFuncAttributeMaxDynamicSharedMemorySize, SMEM_BYTES);

    len_k<<<BB, 256>>>(hmask, pmask);
    conv_premise<<<4096, 256>>>((const float4*)Q);
    prep_hyp<<<dim3(HB / 32, DB / 32, BB), dim3(32, 8)>>>(HYP);
    attn_gemm<0><<<dim3(16, 16, 16), 128, SMEM_BYTES>>>(hmask, nullptr, nullptr);
    rowsum_k<<<BB * PP / 256, 256>>>();
    attn_gemm<1><<<dim3(8, 16, 16), 128, SMEM_BYTES>>>(nullptr, pmask, out);
}

// round 13
// speedup vs baseline: 1.2043x; 1.0115x over previous
#include <cuda_runtime.h>
#include <cuda_fp16.h>
#include <cstdint>

#define BB 16
#define PP 2048
#define HB 2048
#define DB 1024

// ---- device scratch (static __device__ globals) ----
__device__ __half g_Eh[(size_t)BB * PP * HB];    // 128 MB  exp(sim)*mask, fp16
__device__ __half g_Qh[(size_t)BB * PP * DB];    //  64 MB  premise fp16
__device__ __half g_Kh[(size_t)BB * HB * DB];    //  64 MB  hypothesis fp16 [b,h,d]
__device__ __half g_Vth[(size_t)BB * DB * HB];   //  64 MB  hypothesis transposed [b,d,h] fp16
__device__ float g_psum[(size_t)BB * PP * 16];
__device__ int g_hlen[BB];
__device__ int g_plen[BB];

// ---- helpers ----
__device__ __forceinline__ uint32_t smem_u32(const void* p) {
    uint32_t a;
    asm("{ .reg .u64 t; cvta.to.shared.u64 t, %1; cvt.u32.u64 %0, t; }" : "=r"(a) : "l"(p));
    return a;
}

__device__ __forceinline__ void cp_async16(uint32_t dst, const void* src) {
    asm volatile("cp.async.cg.shared.global [%0], [%1], 16;" :: "r"(dst), "l"(src));
}

__device__ __forceinline__ void ldsm4(uint32_t& r0, uint32_t& r1, uint32_t& r2, uint32_t& r3,
                                      uint32_t addr) {
    asm volatile("ldmatrix.sync.aligned.m8n8.x4.shared.b16 {%0,%1,%2,%3}, [%4];"
                 : "=r"(r0), "=r"(r1), "=r"(r2), "=r"(r3) : "r"(addr));
}

__device__ __forceinline__ void mma16(float c[4], uint32_t a0, uint32_t a1, uint32_t a2,
                                      uint32_t a3, uint32_t b0, uint32_t b1) {
    asm volatile(
        "mma.sync.aligned.m16n8k16.row.col.f32.f16.f16.f32 "
        "{%0,%1,%2,%3}, {%4,%5,%6,%7}, {%8,%9}, {%0,%1,%2,%3};\n"
        : "+f"(c[0]), "+f"(c[1]), "+f"(c[2]), "+f"(c[3])
        : "r"(a0), "r"(a1), "r"(a2), "r"(a3), "r"(b0), "r"(b1));
}

// ---------------------------------------------------------------------------
// prep kernels (mask-aware: fully dead regions written as zeros, no read)
// ---------------------------------------------------------------------------
// per-batch valid lengths from the prefix masks (sums of 0/1 are exact)
__global__ __launch_bounds__(256) void len_k(const float* __restrict__ hmask,
                                             const float* __restrict__ pmask) {
    const int b = blockIdx.x, tid = threadIdx.x;
    float s1 = 0.0f, s2 = 0.0f;
    for (int i = tid; i < HB; i += 256) s1 += hmask[(size_t)b * HB + i];
    for (int i = tid; i < PP; i += 256) s2 += pmask[(size_t)b * PP + i];
    __shared__ float r1[256], r2[256];
    r1[tid] = s1; r2[tid] = s2;
    __syncthreads();
    for (int o = 128; o > 0; o >>= 1) {
        if (tid < o) { r1[tid] += r1[tid + o]; r2[tid] += r2[tid + o]; }
        __syncthreads();
    }
    if (tid == 0) {
        g_hlen[b] = (int)(r1[0] + 0.5f);
        g_plen[b] = (int)(r2[0] + 0.5f);
    }
}

__global__ __launch_bounds__(256) void conv_premise(const float4* __restrict__ in) {
    const int b = blockIdx.y;
    const int plen = g_plen[b];
    const int n4 = PP * DB / 4;                    // float4 elems per batch
    uint2* outp = (uint2*)g_Qh + (size_t)b * n4;
    const float4* inb = in + (size_t)b * n4;
    const int stride = gridDim.x * 256;
    for (int i = blockIdx.x * 256 + threadIdx.x; i < n4; i += stride) {
        int p = i >> 8;                             // / (DB/4)
        uint2 o;
        if (p < plen) {
            float4 v = inb[i];
            __half2 lo = __floats2half2_rn(v.x, v.y);
            __half2 hi = __floats2half2_rn(v.z, v.w);
            o.x = *reinterpret_cast<uint32_t*>(&lo);
            o.y = *reinterpret_cast<uint32_t*>(&hi);
        } else {
            o.x = 0u; o.y = 0u;                     // masked rows: zeros (finite, x0 later)
        }
        outp[i] = o;
    }
}

__global__ void prep_hyp(const float* __restrict__ hyp) {
    __shared__ float t[32][33];
    const int b = blockIdx.z;
    const int h0 = blockIdx.x * 32, d0 = blockIdx.y * 32;
    const int tx = threadIdx.x, ty = threadIdx.y;   // (32, 8)
    if (h0 >= g_hlen[b]) {
        // fully dead h-block: write zeros without reading
        __half z = __float2half_rn(0.0f);
#pragma unroll
        for (int i = 0; i < 4; i++) {
            int h = ty + i * 8;
            g_Kh[((size_t)b * HB + h0 + h) * DB + d0 + tx] = z;
            g_Vth[((size_t)b * DB + d0 + ty + i * 8) * HB + h0 + tx] = z;
        }
        return;
    }
#pragma unroll
    for (int i = 0; i < 4; i++) {
        int h = ty + i * 8;
        size_t idx = ((size_t)b * HB + h0 + h) * DB + d0 + tx;
        float v = hyp[idx];
        g_Kh[idx] = __float2half_rn(v);
        t[tx][h] = v;
    }
    __syncthreads();
#pragma unroll
    for (int i = 0; i < 4; i++) {
        int d = ty + i * 8;
        g_Vth[((size_t)b * DB + d0 + d) * HB + h0 + tx] = __float2half_rn(t[d][tx]);
    }
}

// ---------------------------------------------------------------------------
// fp16 mma.sync GEMM. CTA tile 128x128, 4 warps (2x2), warp tile 64x64.
// 32-half k-chunks, dense 64B rows + XOR swizzle (conflict-free stores+ldsm),
// 4-stage cp.async pipeline, 3 CTAs/SM. Mask-aware tile skipping.
// MODE 0: A=g_Qh, B=g_Kh (K=1024). Epilogue: E=exp(acc/32)*hmask -> g_Eh, psum.
// MODE 1: A=g_Eh, B=g_Vth (K trunc to ceil32(hlen)); rowsum computed in
//         prologue from g_psum. out = acc * pmask / rowsum.
// ---------------------------------------------------------------------------
#define OP_B 8192u                 // one operand per stage: 128 rows * 64B
#define STAGE_B 16384u
#define NSTAGE 4
#define RS_OFF (NSTAGE * STAGE_B)              // rowsum cache: 128 floats
#define SMEM_BYTES (NSTAGE * STAGE_B + 512)    // 66048

template <int MODE>
__global__ __launch_bounds__(128, 3) void attn_gemm(const float* __restrict__ hmask,
                                                    const float* __restrict__ pmask,
                                                    float* __restrict__ outp) {
    constexpr int KD = MODE ? HB : DB;       // k extent in halfs
    constexpr int S = KD / 32;

    extern __shared__ float smf[];
    const uint32_t sbase = smem_u32(smf);

    const int tid = threadIdx.x;
    const int x = blockIdx.x, y = blockIdx.y, b = blockIdx.z;
    const int lane = tid & 31, w = tid >> 5;
    const int wm = w >> 1, wn = w & 1;       // 2x2 warps, each 64x64
    const int g = lane >> 2, tg = lane & 3;

    const size_t growbase = (size_t)b * PP + (size_t)y * 128;

    int Send = S;
    if (MODE == 0) {
        if (x * 128 >= g_hlen[b] || y * 128 >= g_plen[b]) return;
    } else {
        if (y * 128 >= g_plen[b]) {
            float4 z = make_float4(0.0f, 0.0f, 0.0f, 0.0f);
            float4* dst = (float4*)(outp + (growbase + tid) * DB + x * 128);
#pragma unroll
            for (int c = 0; c < 32; c++) dst[c] = z;
            return;
        }
        Send = (g_hlen[b] + 31) >> 5;        // E columns beyond hlen are zero
    }

    const __half* Ab = (MODE ? g_Eh : g_Qh) + ((size_t)b * PP + (size_t)y * 128) * KD;
    const __half* Bb = (MODE ? g_Vth : g_Kh) + (size_t)b * (size_t)(HB * DB)
                       + (size_t)x * 128 * KD;

    float acc[4][8][4];
#pragma unroll
    for (int mt = 0; mt < 4; mt++)
#pragma unroll
        for (int nt = 0; nt < 8; nt++)
#pragma unroll
            for (int i = 0; i < 4; i++) acc[mt][nt][i] = 0.0f;

    // cp.async swizzled destination offsets (r = idx>>2, c = idx&3)
    auto load_stage = [&](int s, int buf) {
        if (s < Send) {
            const int kc = s * 32;
            const uint32_t stb = sbase + (uint32_t)buf * STAGE_B;
#pragma unroll
            for (int i = 0; i < 4; i++) {
                int idx = i * 128 + tid;          // 0..511
                int r = idx >> 2, c = idx & 3;
                uint32_t sw = (uint32_t)(c ^ ((r >> 1) & 3));
                uint32_t d = stb + (uint32_t)r * 64 + sw * 16;
                cp_async16(d, Ab + (size_t)r * KD + kc + c * 8);
                cp_async16(d + OP_B, Bb + (size_t)r * KD + kc + c * 8);
            }
        }
        asm volatile("cp.async.commit_group;" ::: "memory");
    };

    load_stage(0, 0);
    load_stage(1, 1);
    load_stage(2, 2);

    // PV: fold rowsum reduction into the prologue (overlaps with cp.async)
    if (MODE == 1) {
        const float* ps = g_psum + (growbase + tid) * 16;
        float s16 = 0.0f;
#pragma unroll
        for (int j = 0; j < 16; j++) s16 += ps[j];
        *(float*)((char*)smf + RS_OFF + tid * 4) = s16;
        // visible to all threads after the first mainloop __syncthreads
    }

    // per-lane ldmatrix byte offsets (swizzle folded in; j toggles ^32)
    const int ra = wm * 64 + (lane & 15);
    const uint32_t a_c0 = (uint32_t)(((lane >> 4) ^ ((ra >> 1) & 3)) & 3);
    const uint32_t a_off0 = (uint32_t)ra * 64 + a_c0 * 16;
    const int rb = wn * 64 + ((lane >> 4) << 3) + (lane & 7);
    const uint32_t b_c0 = (uint32_t)((((lane >> 3) & 1) ^ ((rb >> 1) & 3)) & 3);
    const uint32_t b_off0 = OP_B + (uint32_t)rb * 64 + b_c0 * 16;

#pragma unroll 1
    for (int s = 0; s < Send; s++) {
        asm volatile("cp.async.wait_group 2;" ::: "memory");
        __syncthreads();
        load_stage(s + 3, (s + 3) & 3);

        const uint32_t stb = sbase + (uint32_t)(s & 3) * STAGE_B;
#pragma unroll
        for (int j = 0; j < 2; j++) {
            const uint32_t jx = (uint32_t)j << 5;   // ^32: swizzled k-half toggle
            uint32_t bf[8][2];
#pragma unroll
            for (int ntp = 0; ntp < 4; ntp++) {
                uint32_t q0, q1, q2, q3;
                ldsm4(q0, q1, q2, q3, stb + ((b_off0 + (uint32_t)ntp * 1024) ^ jx));
                bf[2 * ntp][0] = q0; bf[2 * ntp][1] = q1;
                bf[2 * ntp + 1][0] = q2; bf[2 * ntp + 1][1] = q3;
            }
#pragma unroll
            for (int mt = 0; mt < 4; mt++) {
                uint32_t a0, a1, a2, a3;
                ldsm4(a0, a1, a2, a3, stb + ((a_off0 + (uint32_t)mt * 1024) ^ jx));
#pragma unroll
                for (int nt = 0; nt < 8; nt++)
                    mma16(acc[mt][nt], a0, a1, a2, a3, bf[nt][0], bf[nt][1]);
            }
        }
    }

    // ---- epilogue ----
    __syncthreads();

    if (MODE == 0) {
        const float* hm = hmask + (size_t)b * HB + x * 128;
        float ps[4][2];
#pragma unroll
        for (int mt = 0; mt < 4; mt++) { ps[mt][0] = 0.0f; ps[mt][1] = 0.0f; }

#pragma unroll
        for (int mt = 0; mt < 4; mt++) {
            const int r0 = wm * 64 + mt * 16 + g;
#pragma unroll
            for (int nt = 0; nt < 8; nt++) {
                const int col = wn * 64 + nt * 8 + 2 * tg;
                float2 m = *(const float2*)(hm + col);
                float e0 = (m.x != 0.0f) ? __expf(acc[mt][nt][0] * 0.03125f) : 0.0f;
                float e1 = (m.y != 0.0f) ? __expf(acc[mt][nt][1] * 0.03125f) : 0.0f;
                float e2 = (m.x != 0.0f) ? __expf(acc[mt][nt][2] * 0.03125f) : 0.0f;
                float e3 = (m.y != 0.0f) ? __expf(acc[mt][nt][3] * 0.03125f) : 0.0f;
                __half2 h01 = __floats2half2_rn(e0, e1);
                __half2 h23 = __floats2half2_rn(e2, e3);
                *(__half2*)(g_Eh + (growbase + r0) * HB + x * 128 + col) = h01;
                *(__half2*)(g_Eh + (growbase + r0 + 8) * HB + x * 128 + col) = h23;
                float2 f01 = __half22float2(h01);
                float2 f23 = __half22float2(h23);
                ps[mt][0] += f01.x + f01.y;
                ps[mt][1] += f23.x + f23.y;
            }
        }
#pragma unroll
        for (int mt = 0; mt < 4; mt++)
#pragma unroll
            for (int h = 0; h < 2; h++) {
                float v = ps[mt][h];
                v += __shfl_xor_sync(0xFFFFFFFFu, v, 1);
                v += __shfl_xor_sync(0xFFFFFFFFu, v, 2);
                if (tg == 0) {
                    int rloc = wm * 64 + mt * 16 + g + h * 8;
                    smf[rloc * 2 + wn] = v;
                }
            }
        __syncthreads();
        if (tid < 128) {
            float s2 = smf[tid * 2 + 0] + smf[tid * 2 + 1];
            g_psum[(growbase + tid) * 16 + x] = s2;
        }
    } else {
        const float* rs = (const float*)((const char*)smf + RS_OFF);
#pragma unroll
        for (int mt = 0; mt < 4; mt++) {
            const int r0 = wm * 64 + mt * 16 + g;
            const size_t grow0 = growbase + r0, grow1 = growbase + r0 + 8;
            const float pm0 = pmask[grow0], pm1 = pmask[grow1];
            const float s0 = (pm0 != 0.0f) ? pm0 / (rs[r0] + 1e-13f) : 0.0f;
            const float s1 = (pm1 != 0.0f) ? pm1 / (rs[r0 + 8] + 1e-13f) : 0.0f;
#pragma unroll
            for (int nt = 0; nt < 8; nt++) {
                const int col = x * 128 + wn * 64 + nt * 8 + 2 * tg;
                *(float2*)(outp + grow0 * DB + col) =
                    make_float2(acc[mt][nt][0] * s0, acc[mt][nt][1] * s0);
                *(float2*)(outp + grow1 * DB + col) =
                    make_float2(acc[mt][nt][2] * s1, acc[mt][nt][3] * s1);
            }
        }
    }
}

// ---------------------------------------------------------------------------
extern "C" void kernel_launch(void* const* d_in, const int* in_sizes, int n_in,
                              void* d_out, int out_size) {
    const float* Q     = (const float*)d_in[0];  // premise_batch    [B,P,D]
    const float* pmask = (const float*)d_in[1];  // premise_mask     [B,P]
    const float* HYP   = (const float*)d_in[2];  // hypothesis_batch [B,H,D]
    const float* hmask = (const float*)d_in[3];  // hypothesis_mask  [B,H]
    float* out = (float*)d_out;

    cudaFuncSetAttribute(attn_gemm<0>, cudaFuncAttributeMaxDynamicSharedMemorySize, SMEM_BYTES);
    cudaFuncSetAttribute(attn_gemm<1>, cudaFuncAttributeMaxDynamicSharedMemorySize, SMEM_BYTES);

    len_k<<<BB, 256>>>(hmask, pmask);
    conv_premise<<<dim3(1024, BB), 256>>>((const float4*)Q);
    prep_hyp<<<dim3(HB / 32, DB / 32, BB), dim3(32, 8)>>>(HYP);
    attn_gemm<0><<<dim3(16, 16, 16), 128, SMEM_BYTES>>>(hmask, nullptr, nullptr);
    attn_gemm<1><<<dim3(8, 16, 16), 128, SMEM_BYTES>>>(nullptr, pmask, out);
}

// round 14
// speedup vs baseline: 1.2180x; 1.0114x over previous
#include <cuda_runtime.h>
#include <cuda_fp16.h>
#include <cstdint>

#define BB 16
#define PP 2048
#define HB 2048
#define DB 1024

// ---- device scratch (static __device__ globals) ----
__device__ __half g_Eh[(size_t)BB * PP * HB];    // 128 MB  exp(sim)*mask, fp16
__device__ __half g_Qh[(size_t)BB * PP * DB];    //  64 MB  premise fp16
__device__ __half g_Kh[(size_t)BB * HB * DB];    //  64 MB  hypothesis fp16 [b,h,d] (K and V)
__device__ float g_psum[(size_t)BB * PP * 16];
__device__ int g_hlen[BB];
__device__ int g_plen[BB];

// ---- helpers ----
__device__ __forceinline__ uint32_t smem_u32(const void* p) {
    uint32_t a;
    asm("{ .reg .u64 t; cvta.to.shared.u64 t, %1; cvt.u32.u64 %0, t; }" : "=r"(a) : "l"(p));
    return a;
}

__device__ __forceinline__ void cp_async16(uint32_t dst, const void* src) {
    asm volatile("cp.async.cg.shared.global [%0], [%1], 16;" :: "r"(dst), "l"(src));
}

__device__ __forceinline__ void ldsm4(uint32_t& r0, uint32_t& r1, uint32_t& r2, uint32_t& r3,
                                      uint32_t addr) {
    asm volatile("ldmatrix.sync.aligned.m8n8.x4.shared.b16 {%0,%1,%2,%3}, [%4];"
                 : "=r"(r0), "=r"(r1), "=r"(r2), "=r"(r3) : "r"(addr));
}

__device__ __forceinline__ void ldsm4t(uint32_t& r0, uint32_t& r1, uint32_t& r2, uint32_t& r3,
                                       uint32_t addr) {
    asm volatile("ldmatrix.sync.aligned.m8n8.x4.trans.shared.b16 {%0,%1,%2,%3}, [%4];"
                 : "=r"(r0), "=r"(r1), "=r"(r2), "=r"(r3) : "r"(addr));
}

__device__ __forceinline__ void mma16(float c[4], uint32_t a0, uint32_t a1, uint32_t a2,
                                      uint32_t a3, uint32_t b0, uint32_t b1) {
    asm volatile(
        "mma.sync.aligned.m16n8k16.row.col.f32.f16.f16.f32 "
        "{%0,%1,%2,%3}, {%4,%5,%6,%7}, {%8,%9}, {%0,%1,%2,%3};\n"
        : "+f"(c[0]), "+f"(c[1]), "+f"(c[2]), "+f"(c[3])
        : "r"(a0), "r"(a1), "r"(a2), "r"(a3), "r"(b0), "r"(b1));
}

// ---------------------------------------------------------------------------
// prep kernels (mask-aware: fully dead rows written as zeros, no read)
// ---------------------------------------------------------------------------
__global__ __launch_bounds__(256) void len_k(const float* __restrict__ hmask,
                                             const float* __restrict__ pmask) {
    const int b = blockIdx.x, tid = threadIdx.x;
    float s1 = 0.0f, s2 = 0.0f;
    for (int i = tid; i < HB; i += 256) s1 += hmask[(size_t)b * HB + i];
    for (int i = tid; i < PP; i += 256) s2 += pmask[(size_t)b * PP + i];
    __shared__ float r1[256], r2[256];
    r1[tid] = s1; r2[tid] = s2;
    __syncthreads();
    for (int o = 128; o > 0; o >>= 1) {
        if (tid < o) { r1[tid] += r1[tid + o]; r2[tid] += r2[tid + o]; }
        __syncthreads();
    }
    if (tid == 0) {
        g_hlen[b] = (int)(r1[0] + 0.5f);
        g_plen[b] = (int)(r2[0] + 0.5f);
    }
}

// LEN selects which length array gates the rows; DSTQ selects destination.
template <int ISQ>
__global__ __launch_bounds__(256) void conv_fp32_fp16(const float4* __restrict__ in) {
    const int b = blockIdx.y;
    const int rlen = ISQ ? g_plen[b] : g_hlen[b];
    constexpr int RD4 = DB / 4;                    // float4 per row
    constexpr int n4 = (ISQ ? PP : HB) * RD4;
    uint2* outp = (uint2*)(ISQ ? g_Qh : g_Kh) + (size_t)b * n4;
    const float4* inb = in + (size_t)b * n4;
    const int stride = gridDim.x * 256;
    for (int i = blockIdx.x * 256 + threadIdx.x; i < n4; i += stride) {
        int r = i >> 8;                             // / RD4
        uint2 o;
        if (r < rlen) {
            float4 v = inb[i];
            __half2 lo = __floats2half2_rn(v.x, v.y);
            __half2 hi = __floats2half2_rn(v.z, v.w);
            o.x = *reinterpret_cast<uint32_t*>(&lo);
            o.y = *reinterpret_cast<uint32_t*>(&hi);
        } else {
            o.x = 0u; o.y = 0u;                     // masked rows: zeros (finite)
        }
        outp[i] = o;
    }
}

// ---------------------------------------------------------------------------
// fp16 mma.sync GEMM. CTA tile 128x128, 4 warps (2x2), warp tile 64x64.
// 32-half k-chunks, XOR-swizzled conflict-free smem, 4-stage cp.async,
// 3 CTAs/SM. Mask-aware tile skipping.
// MODE 0: A=g_Qh, B=g_Kh k-major (K=1024). E=exp(acc/32)*hmask -> g_Eh, psum.
// MODE 1: A=g_Eh (k-major); B = V read DIRECTLY from g_Kh [h][d] via
//         ldmatrix.trans (32 k-rows x 256B swizzled staging). K trunc to
//         ceil32(hlen); rowsum folded into prologue. out = acc*pmask/rowsum.
// ---------------------------------------------------------------------------
#define OP_B 8192u                 // A stage: 128 rows*64B; B stage: 32 rows*256B (both 8KB)
#define STAGE_B 16384u
#define NSTAGE 4
#define RS_OFF (NSTAGE * STAGE_B)              // rowsum cache: 128 floats
#define SMEM_BYTES (NSTAGE * STAGE_B + 512)    // 66048

template <int MODE>
__global__ __launch_bounds__(128, 3) void attn_gemm(const float* __restrict__ hmask,
                                                    const float* __restrict__ pmask,
                                                    float* __restrict__ outp) {
    constexpr int KD = MODE ? HB : DB;       // k extent in halfs
    constexpr int S = KD / 32;

    extern __shared__ float smf[];
    const uint32_t sbase = smem_u32(smf);

    const int tid = threadIdx.x;
    const int x = blockIdx.x, y = blockIdx.y, b = blockIdx.z;
    const int lane = tid & 31, w = tid >> 5;
    const int wm = w >> 1, wn = w & 1;       // 2x2 warps, each 64x64
    const int g = lane >> 2, tg = lane & 3;

    const size_t growbase = (size_t)b * PP + (size_t)y * 128;

    int Send = S;
    if (MODE == 0) {
        if (x * 128 >= g_hlen[b] || y * 128 >= g_plen[b]) return;
    } else {
        if (y * 128 >= g_plen[b]) {
            float4 z = make_float4(0.0f, 0.0f, 0.0f, 0.0f);
            float4* dst = (float4*)(outp + (growbase + tid) * DB + x * 128);
#pragma unroll
            for (int c = 0; c < 32; c++) dst[c] = z;
            return;
        }
        Send = (g_hlen[b] + 31) >> 5;        // E columns beyond hlen are zero
    }

    const __half* Ab = (MODE ? g_Eh : g_Qh) + ((size_t)b * PP + (size_t)y * 128) * KD;
    // MODE0: B = K rows (k-major, stride DB). MODE1: B = V slice from g_Kh,
    // rows = h (k dim), cols = d; column offset x*128, row offset kc per chunk.
    const __half* Bb = g_Kh + (size_t)b * (size_t)(HB * DB)
                       + (MODE ? (size_t)(x * 128) : (size_t)x * 128 * DB);

    float acc[4][8][4];
#pragma unroll
    for (int mt = 0; mt < 4; mt++)
#pragma unroll
        for (int nt = 0; nt < 8; nt++)
#pragma unroll
            for (int i = 0; i < 4; i++) acc[mt][nt][i] = 0.0f;

    auto load_stage = [&](int s, int buf) {
        if (s < Send) {
            const int kc = s * 32;
            const uint32_t stb = sbase + (uint32_t)buf * STAGE_B;
            // A: 128 rows x 64B, swizzle c ^ ((r>>1)&3)
#pragma unroll
            for (int i = 0; i < 4; i++) {
                int idx = i * 128 + tid;          // 0..511
                int r = idx >> 2, c = idx & 3;
                uint32_t sw = (uint32_t)(c ^ ((r >> 1) & 3));
                cp_async16(stb + (uint32_t)r * 64 + sw * 16,
                           Ab + (size_t)r * KD + kc + c * 8);
            }
            if (MODE == 0) {
                // B: 128 k-major rows x 64B, same swizzle
#pragma unroll
                for (int i = 0; i < 4; i++) {
                    int idx = i * 128 + tid;
                    int r = idx >> 2, c = idx & 3;
                    uint32_t sw = (uint32_t)(c ^ ((r >> 1) & 3));
                    cp_async16(stb + OP_B + (uint32_t)r * 64 + sw * 16,
                               Bb + (size_t)r * DB + kc + c * 8);
                }
            } else {
                // B: V rows kc..kc+31 x 256B, swizzle c16 ^ (r&7)
#pragma unroll
                for (int i = 0; i < 4; i++) {
                    int idx = i * 128 + tid;      // 0..511
                    int r = idx >> 4, c = idx & 15;
                    uint32_t sw = (uint32_t)(c ^ (r & 7));
                    cp_async16(stb + OP_B + (uint32_t)r * 256 + sw * 16,
                               Bb + (size_t)(kc + r) * DB + c * 8);
                }
            }
        }
        asm volatile("cp.async.commit_group;" ::: "memory");
    };

    load_stage(0, 0);
    load_stage(1, 1);
    load_stage(2, 2);

    // PV: fold rowsum reduction into the prologue (overlaps with cp.async)
    if (MODE == 1) {
        const float* ps = g_psum + (growbase + tid) * 16;
        float s16 = 0.0f;
#pragma unroll
        for (int j = 0; j < 16; j++) s16 += ps[j];
        *(float*)((char*)smf + RS_OFF + tid * 4) = s16;
    }

    // A ldmatrix offsets (swizzle folded; j toggles ^32)
    const int ra = wm * 64 + (lane & 15);
    const uint32_t a_c0 = (uint32_t)(((lane >> 4) ^ ((ra >> 1) & 3)) & 3);
    const uint32_t a_off0 = (uint32_t)ra * 64 + a_c0 * 16;
    // B MODE0: k-major n-rows (non-trans)
    const int rb = wn * 64 + ((lane >> 4) << 3) + (lane & 7);
    const uint32_t b_c0 = (uint32_t)((((lane >> 3) & 1) ^ ((rb >> 1) & 3)) & 3);
    const uint32_t b_off0 = OP_B + (uint32_t)rb * 64 + b_c0 * 16;
    // B MODE1: trans from [k][n] rows. lane -> k-row/ n-chunk:
    //   krow = ((lane>>3)&1)*8 + (lane&7); nchunk16 = wn*8 + (lane>>4) (+ntp*2)
    const uint32_t v_row = (uint32_t)((((lane >> 3) & 1) << 3) + (lane & 7));
    const uint32_t v_c0 = (uint32_t)(wn * 8 + (lane >> 4));
    const uint32_t v_key = (uint32_t)(lane & 7);          // = v_row & 7
    const uint32_t v_base = OP_B + v_row * 256;

#pragma unroll 1
    for (int s = 0; s < Send; s++) {
        asm volatile("cp.async.wait_group 2;" ::: "memory");
        __syncthreads();
        load_stage(s + 3, (s + 3) & 3);

        const uint32_t stb = sbase + (uint32_t)(s & 3) * STAGE_B;
#pragma unroll
        for (int j = 0; j < 2; j++) {
            const uint32_t jx = (uint32_t)j << 5;   // A: ^32 swizzled k-half toggle
            uint32_t bf[8][2];
#pragma unroll
            for (int ntp = 0; ntp < 4; ntp++) {
                uint32_t q0, q1, q2, q3;
                if (MODE == 0) {
                    ldsm4(q0, q1, q2, q3, stb + ((b_off0 + (uint32_t)ntp * 1024) ^ jx));
                } else {
                    uint32_t c16 = (v_c0 + (uint32_t)ntp * 2) ^ v_key;
                    ldsm4t(q0, q1, q2, q3,
                           stb + v_base + (uint32_t)j * 4096 + c16 * 16);
                }
                bf[2 * ntp][0] = q0; bf[2 * ntp][1] = q1;
                bf[2 * ntp + 1][0] = q2; bf[2 * ntp + 1][1] = q3;
            }
#pragma unroll
            for (int mt = 0; mt < 4; mt++) {
                uint32_t a0, a1, a2, a3;
                ldsm4(a0, a1, a2, a3, stb + ((a_off0 + (uint32_t)mt * 1024) ^ jx));
#pragma unroll
                for (int nt = 0; nt < 8; nt++)
                    mma16(acc[mt][nt], a0, a1, a2, a3, bf[nt][0], bf[nt][1]);
            }
        }
    }

    // ---- epilogue ----
    __syncthreads();

    if (MODE == 0) {
        const float* hm = hmask + (size_t)b * HB + x * 128;
        float ps[4][2];
#pragma unroll
        for (int mt = 0; mt < 4; mt++) { ps[mt][0] = 0.0f; ps[mt][1] = 0.0f; }

#pragma unroll
        for (int mt = 0; mt < 4; mt++) {
            const int r0 = wm * 64 + mt * 16 + g;
#pragma unroll
            for (int nt = 0; nt < 8; nt++) {
                const int col = wn * 64 + nt * 8 + 2 * tg;
                float2 m = *(const float2*)(hm + col);
                float e0 = (m.x != 0.0f) ? __expf(acc[mt][nt][0] * 0.03125f) : 0.0f;
                float e1 = (m.y != 0.0f) ? __expf(acc[mt][nt][1] * 0.03125f) : 0.0f;
                float e2 = (m.x != 0.0f) ? __expf(acc[mt][nt][2] * 0.03125f) : 0.0f;
                float e3 = (m.y != 0.0f) ? __expf(acc[mt][nt][3] * 0.03125f) : 0.0f;
                __half2 h01 = __floats2half2_rn(e0, e1);
                __half2 h23 = __floats2half2_rn(e2, e3);
                *(__half2*)(g_Eh + (growbase + r0) * HB + x * 128 + col) = h01;
                *(__half2*)(g_Eh + (growbase + r0 + 8) * HB + x * 128 + col) = h23;
                float2 f01 = __half22float2(h01);
                float2 f23 = __half22float2(h23);
                ps[mt][0] += f01.x + f01.y;
                ps[mt][1] += f23.x + f23.y;
            }
        }
#pragma unroll
        for (int mt = 0; mt < 4; mt++)
#pragma unroll
            for (int h = 0; h < 2; h++) {
                float v = ps[mt][h];
                v += __shfl_xor_sync(0xFFFFFFFFu, v, 1);
                v += __shfl_xor_sync(0xFFFFFFFFu, v, 2);
                if (tg == 0) {
                    int rloc = wm * 64 + mt * 16 + g + h * 8;
                    smf[rloc * 2 + wn] = v;
                }
            }
        __syncthreads();
        if (tid < 128) {
            float s2 = smf[tid * 2 + 0] + smf[tid * 2 + 1];
            g_psum[(growbase + tid) * 16 + x] = s2;
        }
    } else {
        const float* rs = (const float*)((const char*)smf + RS_OFF);
#pragma unroll
        for (int mt = 0; mt < 4; mt++) {
            const int r0 = wm * 64 + mt * 16 + g;
            const size_t grow0 = growbase + r0, grow1 = growbase + r0 + 8;
            const float pm0 = pmask[grow0], pm1 = pmask[grow1];
            const float s0 = (pm0 != 0.0f) ? pm0 / (rs[r0] + 1e-13f) : 0.0f;
            const float s1 = (pm1 != 0.0f) ? pm1 / (rs[r0 + 8] + 1e-13f) : 0.0f;
#pragma unroll
            for (int nt = 0; nt < 8; nt++) {
                const int col = x * 128 + wn * 64 + nt * 8 + 2 * tg;
                *(float2*)(outp + grow0 * DB + col) =
                    make_float2(acc[mt][nt][0] * s0, acc[mt][nt][1] * s0);
                *(float2*)(outp + grow1 * DB + col) =
                    make_float2(acc[mt][nt][2] * s1, acc[mt][nt][3] * s1);
            }
        }
    }
}

// ---------------------------------------------------------------------------
extern "C" void kernel_launch(void* const* d_in, const int* in_sizes, int n_in,
                              void* d_out, int out_size) {
    const float* Q     = (const float*)d_in[0];  // premise_batch    [B,P,D]
    const float* pmask = (const float*)d_in[1];  // premise_mask     [B,P]
    const float* HYP   = (const float*)d_in[2];  // hypothesis_batch [B,H,D]
    const float* hmask = (const float*)d_in[3];  // hypothesis_mask  [B,H]
    float* out = (float*)d_out;

    cudaFuncSetAttribute(attn_gemm<0>, cudaFuncAttributeMaxDynamicSharedMemorySize, SMEM_BYTES);
    cudaFuncSetAttribute(attn_gemm<1>, cudaFuncAttributeMaxDynamicSharedMemorySize, SMEM_BYTES);

    len_k<<<BB, 256>>>(hmask, pmask);
    conv_fp32_fp16<1><<<dim3(1024, BB), 256>>>((const float4*)Q);
    conv_fp32_fp16<0><<<dim3(1024, BB), 256>>>((const float4*)HYP);
    attn_gemm<0><<<dim3(16, 16, 16), 128, SMEM_BYTES>>>(hmask, nullptr, nullptr);
    attn_gemm<1><<<dim3(8, 16, 16), 128, SMEM_BYTES>>>(nullptr, pmask, out);
}